// round 15
// baseline (speedup 1.0000x reference)
#include <cuda_runtime.h>
#include <cuda_fp16.h>
#include <cstdint>

#define B_    4
#define C_    128
#define H_    256
#define W_    256
#define GW    28
#define QB    784
#define Q_    3136
#define NPOS  29
#define NNEG  80
#define NOFF  109
#define ND    3136
#define NCOL  3217   /* 1 + 80 + 3136 */
#define MPAD  3200   /* 25 * 128 */
#define KSP   256    /* 2 * 128 : [hiA|loA] x [hiB|hiB]  (fp16 split) */

static const size_t S_SCORES = (size_t)Q_ * NCOL;   // 10,088,512

// ---------------- offsets, exact reference enumeration order (j outer asc, i inner asc)
__constant__ int c_off[NOFF][2] = {
    // ---- 29 positives ----
    {0,-3},
    {-2,-2},{-1,-2},{0,-2},{1,-2},{2,-2},
    {-2,-1},{-1,-1},{0,-1},{1,-1},{2,-1},
    {-3,0},{-2,0},{-1,0},{0,0},{1,0},{2,0},{3,0},
    {-2,1},{-1,1},{0,1},{1,1},{2,1},
    {-2,2},{-1,2},{0,2},{1,2},{2,2},
    {0,3},
    // ---- 80 negatives ----
    {0,-7},
    {-3,-6},{-2,-6},{-1,-6},{0,-6},{1,-6},{2,-6},{3,-6},
    {-4,-5},{-3,-5},{-2,-5},{-1,-5},{0,-5},{1,-5},{2,-5},{3,-5},{4,-5},
    {-5,-4},{-4,-4},{-3,-4},{3,-4},{4,-4},{5,-4},
    {-6,-3},{-5,-3},{-4,-3},{4,-3},{5,-3},{6,-3},
    {-6,-2},{-5,-2},{5,-2},{6,-2},
    {-6,-1},{-5,-1},{5,-1},{6,-1},
    {-7,0},{-6,0},{-5,0},{5,0},{6,0},{7,0},
    {-6,1},{-5,1},{5,1},{6,1},
    {-6,2},{-5,2},{5,2},{6,2},
    {-6,3},{-5,3},{-4,3},{4,3},{5,3},{6,3},
    {-5,4},{-4,4},{-3,4},{3,4},{4,4},{5,4},
    {-4,5},{-3,5},{-2,5},{-1,5},{0,5},{1,5},{2,5},{3,5},{4,5},
    {-3,6},{-2,6},{-1,6},{0,6},{1,6},{2,6},{3,6},
    {0,7}
};

// ---------------- device scratch ----------------
__device__ __half g_feat2t[(size_t)B_ * H_ * W_ * C_];      // feat2 -> (B,H,W,C), fp16
__device__ __half g_a[(size_t)MPAD * KSP];                  // split queries [hi|lo]
__device__ __half g_b[(size_t)MPAD * KSP];                  // distractors   [hi|hi]
__device__ int2  g_xy2[Q_];

// ---------------- helpers ----------------
__device__ __forceinline__ void ldsm_x4(uint32_t (&r)[4], const void* p) {
    uint32_t a = (uint32_t)__cvta_generic_to_shared(p);
    asm volatile("ldmatrix.sync.aligned.m8n8.x4.shared.b16 {%0,%1,%2,%3}, [%4];"
        : "=r"(r[0]), "=r"(r[1]), "=r"(r[2]), "=r"(r[3]) : "r"(a));
}
__device__ __forceinline__ void mma_f16(float (&d)[4], const uint32_t (&a)[4],
                                        uint32_t b0, uint32_t b1) {
    asm volatile("mma.sync.aligned.m16n8k16.row.col.f32.f16.f16.f32 "
        "{%0,%1,%2,%3}, {%4,%5,%6,%7}, {%8,%9}, {%0,%1,%2,%3};"
        : "+f"(d[0]), "+f"(d[1]), "+f"(d[2]), "+f"(d[3])
        : "r"(a[0]), "r"(a[1]), "r"(a[2]), "r"(a[3]), "r"(b0), "r"(b1));
}

// ---------------- transpose feat2 (B,C,H,W) fp32 -> (B,HW,C) fp16, 64-pixel tiles
__global__ void k_transpose(const float* __restrict__ f2) {
    __shared__ float tile[32][65];
    int b  = blockIdx.z;
    int p0 = blockIdx.x * 64;     // pixel (h*W+w)
    int c0 = blockIdx.y * 32;     // channel
    int tx = threadIdx.x, ty = threadIdx.y;     // 32 x 8
    const float* src = f2 + (size_t)b * C_ * H_ * W_;
    __half* dst = g_feat2t + (size_t)b * H_ * W_ * C_;
#pragma unroll
    for (int i = 0; i < 32; i += 8) {
        tile[ty + i][tx]      = src[(size_t)(c0 + ty + i) * (H_ * W_) + p0 + tx];
        tile[ty + i][tx + 32] = src[(size_t)(c0 + ty + i) * (H_ * W_) + p0 + 32 + tx];
    }
    __syncthreads();
#pragma unroll
    for (int i = 0; i < 8; i++)
        dst[(size_t)(p0 + ty + 8 * i) * C_ + c0 + tx] = __float2half(tile[tx][ty + 8 * i]);
}

// ---------------- per-query: 512 threads / 16 warps.
// Offsets phase: 4 iterations, 2 offsets per warp, warp-uniform shuffles.
__global__ void __launch_bounds__(512) k_posneg(const float* __restrict__ feat1,
                                                const float* __restrict__ conf1,
                                                const float* __restrict__ conf2,
                                                const float* __restrict__ aflow,
                                                float* __restrict__ out) {
    int q   = blockIdx.x;
    int tid = threadIdx.x;
    int b = q / QB;
    int r = q % QB;
    int y = 16 + (r / GW) * 8;
    int x = 16 + (r % GW) * 8;

    __shared__ __align__(16) float f1s[C_];
    __shared__ float pos_s[NPOS];
    __shared__ int2  sxy;

    if (tid < C_) {
        // f1 gather (strided over channels) + fp16 hi/lo split
        float f1v = feat1[(((size_t)b * C_ + tid) * H_ + y) * W_ + x];
        f1s[tid] = f1v;
        __half hi = __float2half(f1v);
        __half lo = __float2half(f1v - __half2float(hi));
        __half* arow = g_a + (size_t)q * KSP;
        arow[tid] = hi; arow[128 + tid] = lo;
        // distractor feature gather: feat2t already fp16 == fp16(feat2) — bit-identical B operand
        __half hv = g_feat2t[(((size_t)b * H_ + y) * W_ + x) * C_ + tid];
        __half* brow = g_b + (size_t)q * KSP;
        brow[tid] = hv; brow[128 + tid] = hv;
    }
    if (tid >= 128 && tid < 128 + 81)
        out[S_SCORES + (size_t)q * NCOL + (tid - 128)] = (tid == 128) ? 1.0f : 0.0f;
    if (tid == 0) {
        float ax = aflow[(((size_t)b * 2 + 0) * H_ + y) * W_ + x];
        float ay = aflow[(((size_t)b * 2 + 1) * H_ + y) * W_ + x];
        int x2 = (int)(ax + 0.5f);
        int y2 = (int)(ay + 0.5f);
        sxy = make_int2(x2, y2);
        g_xy2[q] = sxy;
        bool m = (x2 >= 0) && (y2 >= 0) && (x2 < W_) && (y2 < H_);
        out[2 * S_SCORES + q] = m ? 1.0f : 0.0f;
    }
    __syncthreads();

    int2 xy2 = sxy;
    int lane = tid & 31, warp = tid >> 5;     // 16 warps
    const __half* f2b = g_feat2t + (size_t)b * H_ * W_ * C_;
    const float4* f1v4 = (const float4*)f1s;
    float4 a = f1v4[lane];          // lane owns channels 4*lane..4*lane+3

    // lane reads 4 halves (8B) per patch pixel
    #define GADDR(off) ((const uint2*)(f2b + ((size_t)min(max(xy2.y + c_off[min((off), NOFF-1)][1], 0), H_ - 1) * W_ \
                         + min(max(xy2.x + c_off[min((off), NOFF-1)][0], 0), W_ - 1)) * C_) + lane)
    // warp w handles offset pairs {32*i + 2w, 32*i + 2w + 1}, i = 0..3
    uint2 v0 = *GADDR(2 * warp);
    uint2 v1 = *GADDR(2 * warp + 1);
#pragma unroll
    for (int i = 0; i < 4; i++) {
        int o0 = 32 * i + 2 * warp;
        uint2 n0, n1;
        if (i < 3) {
            n0 = *GADDR(o0 + 32);
            n1 = *GADDR(o0 + 33);
        }
        const __half2* h0 = (const __half2*)&v0;
        const __half2* h1 = (const __half2*)&v1;
        float2 p00 = __half22float2(h0[0]), p01 = __half22float2(h0[1]);
        float2 p10 = __half22float2(h1[0]), p11 = __half22float2(h1[1]);
        float s0 = p00.x * a.x + p00.y * a.y + p01.x * a.z + p01.y * a.w;
        float s1 = p10.x * a.x + p10.y * a.y + p11.x * a.z + p11.y * a.w;
        s0 += __shfl_xor_sync(0xffffffffu, s0, 16);
        s1 += __shfl_xor_sync(0xffffffffu, s1, 16);
        s0 += __shfl_xor_sync(0xffffffffu, s0, 8);
        s1 += __shfl_xor_sync(0xffffffffu, s1, 8);
        s0 += __shfl_xor_sync(0xffffffffu, s0, 4);
        s1 += __shfl_xor_sync(0xffffffffu, s1, 4);
        s0 += __shfl_xor_sync(0xffffffffu, s0, 2);
        s1 += __shfl_xor_sync(0xffffffffu, s1, 2);
        s0 += __shfl_xor_sync(0xffffffffu, s0, 1);
        s1 += __shfl_xor_sync(0xffffffffu, s1, 1);
        if (lane == 0) {
            if (o0 < NOFF) {
                if (o0 < NPOS) pos_s[o0] = s0;
                else out[(size_t)q * NCOL + 1 + (o0 - NPOS)] = s0;
            }
            if (o0 + 1 < NOFF) {
                if (o0 + 1 < NPOS) pos_s[o0 + 1] = s1;
                else out[(size_t)q * NCOL + 1 + (o0 + 1 - NPOS)] = s1;
            }
        }
        v0 = n0; v1 = n1;
    }
    #undef GADDR
    __syncthreads();

    if (tid == 0) {
        float best = pos_s[0];
        int bi = 0;
        for (int p = 1; p < NPOS; p++)
            if (pos_s[p] > best) { best = pos_s[p]; bi = p; }
        out[(size_t)q * NCOL] = best;
        int sx = min(max(xy2.x + c_off[bi][0], 0), W_ - 1);
        int sy = min(max(xy2.y + c_off[bi][1], 0), H_ - 1);
        float c1 = conf1[((size_t)b * H_ + y)  * W_ + x];
        float c2 = conf2[((size_t)b * H_ + sy) * W_ + sx];
        out[2 * S_SCORES + Q_ + q] = 0.5f * (c1 + c2);
    }
}

// ---------------- dscores GEMM: fp16 tensor cores, K=256 split, mask+gt fused
// As/Bs padded to 24 halves per row (48B) -> conflict-free LDSM. (unchanged from R14)
#define LDP 24
__global__ void __launch_bounds__(256) k_gemm(float* __restrict__ out) {
    __shared__ __align__(16) __half As[2][128][LDP];
    __shared__ __align__(16) __half Bs[2][128][LDP];
    __shared__ float sbuf[32][132];                 // epilogue staging
    __shared__ int scx[128], scy[128], scb[128];    // col (distractor) coords
    __shared__ int srx[128], sry[128], srb[128];    // row (query) xy2/batch

    int t  = threadIdx.x;
    int q0 = blockIdx.y * 128;
    int d0 = blockIdx.x * 128;

    if (t < 128) {
        int d = min(d0 + t, ND - 1);
        int b3 = d / QB, rd = d % QB;
        scb[t] = b3;
        scy[t] = 16 + (rd / GW) * 8;
        scx[t] = 16 + (rd % GW) * 8;
        int q = min(q0 + t, Q_ - 1);
        int2 xy = g_xy2[q];
        srx[t] = xy.x; sry[t] = xy.y; srb[t] = q / QB;
    }

    int warp = t >> 5, lane = t & 31;
    int wm = warp & 3;        // 4 warps along M (32 rows each)
    int wn = warp >> 2;       // 2 warps along N (64 cols each)

    // per-thread staging addresses (two 16B segments for A and B each)
    int row0 = t >> 2,          seg0 = t & 3;
    int row1 = (t + 256) >> 2,  seg1 = (t + 256) & 3;
    const __half* srcA0 = &g_a[(size_t)min(q0 + row0, Q_ - 1) * KSP + seg0 * 8];
    const __half* srcB0 = &g_b[(size_t)min(d0 + row0, ND - 1) * KSP + seg0 * 8];
    const __half* srcA1 = &g_a[(size_t)min(q0 + row1, Q_ - 1) * KSP + seg1 * 8];
    const __half* srcB1 = &g_b[(size_t)min(d0 + row1, ND - 1) * KSP + seg1 * 8];

    float acc[2][8][4];
#pragma unroll
    for (int i = 0; i < 2; i++)
#pragma unroll
        for (int j = 0; j < 8; j++)
#pragma unroll
            for (int c = 0; c < 4; c++) acc[i][j][c] = 0.0f;

    uint4 ra0 = *(const uint4*)(srcA0);
    uint4 rb0 = *(const uint4*)(srcB0);
    uint4 ra1 = *(const uint4*)(srcA1);
    uint4 rb1 = *(const uint4*)(srcB1);

    for (int kc = 0; kc < KSP; kc += 32) {
        __syncthreads();            // previous chunk's compute finished
        *(uint4*)&As[seg0 >> 1][row0][(seg0 & 1) * 8] = ra0;
        *(uint4*)&Bs[seg0 >> 1][row0][(seg0 & 1) * 8] = rb0;
        *(uint4*)&As[seg1 >> 1][row1][(seg1 & 1) * 8] = ra1;
        *(uint4*)&Bs[seg1 >> 1][row1][(seg1 & 1) * 8] = rb1;
        __syncthreads();            // staging visible
        if (kc + 32 < KSP) {        // prefetch next chunk (overlaps MMA below)
            ra0 = *(const uint4*)(srcA0 + kc + 32);
            rb0 = *(const uint4*)(srcB0 + kc + 32);
            ra1 = *(const uint4*)(srcA1 + kc + 32);
            rb1 = *(const uint4*)(srcB1 + kc + 32);
        }
#pragma unroll
        for (int s = 0; s < 2; s++) {
            uint32_t af[2][4], bf[4][4];
            int rsel = lane & 15;
            int csel = (lane >> 4) * 8;
#pragma unroll
            for (int i = 0; i < 2; i++)
                ldsm_x4(af[i], &As[s][wm * 32 + i * 16 + rsel][csel]);
#pragma unroll
            for (int j4 = 0; j4 < 4; j4++)
                ldsm_x4(bf[j4], &Bs[s][wn * 64 + j4 * 16 + rsel][csel]);
#pragma unroll
            for (int i = 0; i < 2; i++)
#pragma unroll
                for (int j = 0; j < 8; j++)
                    mma_f16(acc[i][j], af[i], bf[j >> 1][j & 1], bf[j >> 1][(j & 1) + 2]);
        }
    }
    __syncthreads();

    // epilogue: 4 chunks of 32 rows; stage via smem, emit lane-contiguous stores
    int group = lane >> 2, tig = lane & 3;
#pragma unroll 1
    for (int w = 0; w < 4; w++) {
        if (wm == w) {
#pragma unroll
            for (int i = 0; i < 2; i++)
#pragma unroll
                for (int j = 0; j < 8; j++)
#pragma unroll
                    for (int c = 0; c < 4; c++) {
                        int rl = i * 16 + group + (c >> 1) * 8;
                        int cl = wn * 64 + j * 8 + tig * 2 + (c & 1);
                        sbuf[rl][cl] = acc[i][j][c];
                    }
        }
        __syncthreads();
        // readout: each warp owns 4 rows; lanes contiguous over columns
#pragma unroll
        for (int r4 = 0; r4 < 4; r4++) {
            int rl = warp * 4 + r4;
            int q  = q0 + w * 32 + rl;
            if (q < Q_) {
                int qx = srx[w * 32 + rl], qy = sry[w * 32 + rl], qb = srb[w * 32 + rl];
                float* so = out + (size_t)q * NCOL + 1 + NNEG;
                float* go = out + S_SCORES + (size_t)q * NCOL + 1 + NNEG;
#pragma unroll
                for (int c4 = 0; c4 < 4; c4++) {
                    int col = c4 * 32 + lane;
                    int d = d0 + col;
                    if (d0 + c4 * 32 < ND) {       // chunk-uniform validity (32 | ND-d0)
                        int dx = scx[col] - qx, dy = scy[col] - qy;
                        int dis2 = dx * dx + dy * dy + (scb[col] != qb ? 25 : 0);
                        so[d] = (dis2 < 25) ? 0.0f : sbuf[rl][col];
                        go[d] = 0.0f;
                    }
                }
            }
        }
        __syncthreads();
    }
}

// ---------------- launch ----------------
extern "C" void kernel_launch(void* const* d_in, const int* in_sizes, int n_in,
                              void* d_out, int out_size) {
    const float* feat1 = (const float*)d_in[0];
    const float* feat2 = (const float*)d_in[1];
    const float* conf1 = (const float*)d_in[2];
    const float* conf2 = (const float*)d_in[3];
    const float* aflow = (const float*)d_in[4];
    float* out = (float*)d_out;
    (void)in_sizes; (void)n_in; (void)out_size;

    dim3 tb(32, 8);
    dim3 tg((H_ * W_) / 64, C_ / 32, B_);
    k_transpose<<<tg, tb>>>(feat2);

    k_posneg<<<Q_, 512>>>(feat1, conf1, conf2, aflow, out);

    dim3 gg(MPAD / 128, MPAD / 128);
    k_gemm<<<gg, 256>>>(out);
}

// round 17
// speedup vs baseline: 1.0810x; 1.0810x over previous
#include <cuda_runtime.h>
#include <cuda_fp16.h>
#include <cstdint>

#define B_    4
#define C_    128
#define H_    256
#define W_    256
#define GW    28
#define QB    784
#define Q_    3136
#define NPOS  29
#define NNEG  80
#define NOFF  109
#define ND    3136
#define NCOL  3217   /* 1 + 80 + 3136 */
#define MPAD  3200   /* 25 * 128 */
#define KSP   256    /* 2 * 128 : [hiA|loA] x [hiB|hiB]  (fp16 split) */
#define NTB   16384  /* transpose blocks: (HW/64) * (C/32) * B = 1024*4*4 */

static const size_t S_SCORES = (size_t)Q_ * NCOL;   // 10,088,512

// ---------------- offsets, exact reference enumeration order (j outer asc, i inner asc)
__constant__ int c_off[NOFF][2] = {
    // ---- 29 positives ----
    {0,-3},
    {-2,-2},{-1,-2},{0,-2},{1,-2},{2,-2},
    {-2,-1},{-1,-1},{0,-1},{1,-1},{2,-1},
    {-3,0},{-2,0},{-1,0},{0,0},{1,0},{2,0},{3,0},
    {-2,1},{-1,1},{0,1},{1,1},{2,1},
    {-2,2},{-1,2},{0,2},{1,2},{2,2},
    {0,3},
    // ---- 80 negatives ----
    {0,-7},
    {-3,-6},{-2,-6},{-1,-6},{0,-6},{1,-6},{2,-6},{3,-6},
    {-4,-5},{-3,-5},{-2,-5},{-1,-5},{0,-5},{1,-5},{2,-5},{3,-5},{4,-5},
    {-5,-4},{-4,-4},{-3,-4},{3,-4},{4,-4},{5,-4},
    {-6,-3},{-5,-3},{-4,-3},{4,-3},{5,-3},{6,-3},
    {-6,-2},{-5,-2},{5,-2},{6,-2},
    {-6,-1},{-5,-1},{5,-1},{6,-1},
    {-7,0},{-6,0},{-5,0},{5,0},{6,0},{7,0},
    {-6,1},{-5,1},{5,1},{6,1},
    {-6,2},{-5,2},{5,2},{6,2},
    {-6,3},{-5,3},{-4,3},{4,3},{5,3},{6,3},
    {-5,4},{-4,4},{-3,4},{3,4},{4,4},{5,4},
    {-4,5},{-3,5},{-2,5},{-1,5},{0,5},{1,5},{2,5},{3,5},{4,5},
    {-3,6},{-2,6},{-1,6},{0,6},{1,6},{2,6},{3,6},
    {0,7}
};

// ---------------- device scratch ----------------
__device__ __half g_feat2t[(size_t)B_ * H_ * W_ * C_];      // feat2 -> (B,H,W,C), fp16
__device__ __half g_a[(size_t)MPAD * KSP];                  // split queries [hi|lo]
__device__ __half g_b[(size_t)MPAD * KSP];                  // distractors   [hi|hi]
__device__ int2  g_xy2[Q_];
__device__ float g_c1[Q_];                                  // conf1 at query points

// ---------------- helpers ----------------
__device__ __forceinline__ void ldsm_x4(uint32_t (&r)[4], const void* p) {
    uint32_t a = (uint32_t)__cvta_generic_to_shared(p);
    asm volatile("ldmatrix.sync.aligned.m8n8.x4.shared.b16 {%0,%1,%2,%3}, [%4];"
        : "=r"(r[0]), "=r"(r[1]), "=r"(r[2]), "=r"(r[3]) : "r"(a));
}
__device__ __forceinline__ void mma_f16(float (&d)[4], const uint32_t (&a)[4],
                                        uint32_t b0, uint32_t b1) {
    asm volatile("mma.sync.aligned.m16n8k16.row.col.f32.f16.f16.f32 "
        "{%0,%1,%2,%3}, {%4,%5,%6,%7}, {%8,%9}, {%0,%1,%2,%3};"
        : "+f"(d[0]), "+f"(d[1]), "+f"(d[2]), "+f"(d[3])
        : "r"(a[0]), "r"(a[1]), "r"(a[2]), "r"(a[3]), "r"(b0), "r"(b1));
}

// ---------------- fused: transpose (blocks < NTB) + query prep (blocks >= NTB)
// Prep needs nothing from the transpose, so the two run concurrently: the
// latency-bound feat1 strided gather hides inside the transpose's DRAM shadow.
__global__ void __launch_bounds__(256) k_trans_prep(const float* __restrict__ f2,
                                                    const float* __restrict__ feat1,
                                                    const float* __restrict__ conf1,
                                                    const float* __restrict__ aflow,
                                                    float* __restrict__ out) {
    int bid = blockIdx.x;
    int tid = threadIdx.x;

    if (bid < NTB) {
        // ---- transpose feat2 (B,C,H,W) fp32 -> (B,HW,C) fp16, 64-pixel tiles
        __shared__ float tile[32][65];
        int p0 = (bid & 1023) * 64;          // pixel base
        int c0 = ((bid >> 10) & 3) * 32;     // channel base
        int b  = bid >> 12;                  // batch
        int tx = tid & 31, ty = tid >> 5;    // 32 x 8
        const float* src = f2 + (size_t)b * C_ * H_ * W_;
        __half* dst = g_feat2t + (size_t)b * H_ * W_ * C_;
#pragma unroll
        for (int i = 0; i < 32; i += 8) {
            tile[ty + i][tx]      = src[(size_t)(c0 + ty + i) * (H_ * W_) + p0 + tx];
            tile[ty + i][tx + 32] = src[(size_t)(c0 + ty + i) * (H_ * W_) + p0 + 32 + tx];
        }
        __syncthreads();
#pragma unroll
        for (int i = 0; i < 8; i++)
            dst[(size_t)(p0 + ty + 8 * i) * C_ + c0 + tx] = __float2half(tile[tx][ty + 8 * i]);
    } else {
        // ---- per-query prep (independent of feat2t)
        int q = bid - NTB;
        int b = q / QB;
        int r = q % QB;
        int y = 16 + (r / GW) * 8;
        int x = 16 + (r % GW) * 8;

        if (tid < C_) {
            float f1v = feat1[(((size_t)b * C_ + tid) * H_ + y) * W_ + x];
            __half hi = __float2half(f1v);
            __half lo = __float2half(f1v - __half2float(hi));
            __half* arow = g_a + (size_t)q * KSP;
            arow[tid] = hi; arow[128 + tid] = lo;
        }
        if (tid >= 128 && tid < 128 + 81)   // gt columns 0..80: [1, 0 x 80]
            out[S_SCORES + (size_t)q * NCOL + (tid - 128)] = (tid == 128) ? 1.0f : 0.0f;
        if (tid == 224) {
            float ax = aflow[(((size_t)b * 2 + 0) * H_ + y) * W_ + x];
            float ay = aflow[(((size_t)b * 2 + 1) * H_ + y) * W_ + x];
            int x2 = (int)(ax + 0.5f);
            int y2 = (int)(ay + 0.5f);
            g_xy2[q] = make_int2(x2, y2);
            bool m = (x2 >= 0) && (y2 >= 0) && (x2 < W_) && (y2 < H_);
            out[2 * S_SCORES + q] = m ? 1.0f : 0.0f;
        }
        if (tid == 225)
            g_c1[q] = conf1[((size_t)b * H_ + y) * W_ + x];
    }
}

// ---------------- per-query: f1 from g_a (hi+lo), g_b production, pos/neg scores,
// parallel first-occurrence argmax, qconf.  Offsets phase = R14 structure.
__global__ void __launch_bounds__(256) k_posneg(const float* __restrict__ conf2,
                                                float* __restrict__ out) {
    int q   = blockIdx.x;
    int tid = threadIdx.x;
    int b = q / QB;
    int r = q % QB;
    int y = 16 + (r / GW) * 8;
    int x = 16 + (r % GW) * 8;

    __shared__ __align__(16) float f1s[C_];
    __shared__ float pos_s[NPOS];

    if (tid < C_) {
        // f1 reconstructed exactly as hi + lo (error ~2^-22, negligible)
        const __half* arow = g_a + (size_t)q * KSP;
        f1s[tid] = __half2float(arow[tid]) + __half2float(arow[128 + tid]);
        // distractor feature gather: feat2t already fp16 — bit-identical B operand
        __half hv = g_feat2t[(((size_t)b * H_ + y) * W_ + x) * C_ + tid];
        __half* brow = g_b + (size_t)q * KSP;
        brow[tid] = hv; brow[128 + tid] = hv;
    }
    int2 xy2 = g_xy2[q];
    __syncthreads();

    int lane = tid & 31, warp = tid >> 5;     // 8 warps
    const __half* f2b = g_feat2t + (size_t)b * H_ * W_ * C_;
    const float4* f1v4 = (const float4*)f1s;
    float4 a = f1v4[lane];          // lane owns channels 4*lane..4*lane+3

    #define GADDR(off) ((const uint2*)(f2b + ((size_t)min(max(xy2.y + c_off[min((off), NOFF-1)][1], 0), H_ - 1) * W_ \
                         + min(max(xy2.x + c_off[min((off), NOFF-1)][0], 0), W_ - 1)) * C_) + lane)
    uint2 v0 = *GADDR(2 * warp);
    uint2 v1 = *GADDR(2 * warp + 1);
#pragma unroll
    for (int i = 0; i < 7; i++) {
        int o0 = 16 * i + 2 * warp;
        uint2 n0, n1;
        if (i < 6) {
            n0 = *GADDR(o0 + 16);
            n1 = *GADDR(o0 + 17);
        }
        const __half2* h0 = (const __half2*)&v0;
        const __half2* h1 = (const __half2*)&v1;
        float2 p00 = __half22float2(h0[0]), p01 = __half22float2(h0[1]);
        float2 p10 = __half22float2(h1[0]), p11 = __half22float2(h1[1]);
        float s0 = p00.x * a.x + p00.y * a.y + p01.x * a.z + p01.y * a.w;
        float s1 = p10.x * a.x + p10.y * a.y + p11.x * a.z + p11.y * a.w;
        s0 += __shfl_xor_sync(0xffffffffu, s0, 16);
        s1 += __shfl_xor_sync(0xffffffffu, s1, 16);
        s0 += __shfl_xor_sync(0xffffffffu, s0, 8);
        s1 += __shfl_xor_sync(0xffffffffu, s1, 8);
        s0 += __shfl_xor_sync(0xffffffffu, s0, 4);
        s1 += __shfl_xor_sync(0xffffffffu, s1, 4);
        s0 += __shfl_xor_sync(0xffffffffu, s0, 2);
        s1 += __shfl_xor_sync(0xffffffffu, s1, 2);
        s0 += __shfl_xor_sync(0xffffffffu, s0, 1);
        s1 += __shfl_xor_sync(0xffffffffu, s1, 1);
        if (lane == 0) {
            if (o0 < NOFF) {
                if (o0 < NPOS) pos_s[o0] = s0;
                else out[(size_t)q * NCOL + 1 + (o0 - NPOS)] = s0;
            }
            if (o0 + 1 < NOFF) {
                if (o0 + 1 < NPOS) pos_s[o0 + 1] = s1;
                else out[(size_t)q * NCOL + 1 + (o0 + 1 - NPOS)] = s1;
            }
        }
        v0 = n0; v1 = n1;
    }
    #undef GADDR
    __syncthreads();

    // warp 0: parallel first-occurrence argmax over the 29 positives
    if (warp == 0) {
        float v = (lane < NPOS) ? pos_s[lane] : -3.4e38f;
        int   bi = (lane < NPOS) ? lane : NPOS;
#pragma unroll
        for (int d = 16; d > 0; d >>= 1) {
            float ov = __shfl_xor_sync(0xffffffffu, v, d);
            int   oi = __shfl_xor_sync(0xffffffffu, bi, d);
            if (ov > v || (ov == v && oi < bi)) { v = ov; bi = oi; }
        }
        if (lane == 0) {
            out[(size_t)q * NCOL] = v;                          // pscores
            int sx = min(max(xy2.x + c_off[bi][0], 0), W_ - 1);
            int sy = min(max(xy2.y + c_off[bi][1], 0), H_ - 1);
            float c2 = conf2[((size_t)b * H_ + sy) * W_ + sx];
            out[2 * S_SCORES + Q_ + q] = 0.5f * (g_c1[q] + c2);  // qconf
        }
    }
}

// ---------------- dscores GEMM: fp16 tensor cores, K=256 split, mask+gt fused
// As/Bs padded to 24 halves per row (48B) -> conflict-free LDSM. (unchanged from R14)
#define LDP 24
__global__ void __launch_bounds__(256) k_gemm(float* __restrict__ out) {
    __shared__ __align__(16) __half As[2][128][LDP];
    __shared__ __align__(16) __half Bs[2][128][LDP];
    __shared__ float sbuf[32][132];                 // epilogue staging
    __shared__ int scx[128], scy[128], scb[128];    // col (distractor) coords
    __shared__ int srx[128], sry[128], srb[128];    // row (query) xy2/batch

    int t  = threadIdx.x;
    int q0 = blockIdx.y * 128;
    int d0 = blockIdx.x * 128;

    if (t < 128) {
        int d = min(d0 + t, ND - 1);
        int b3 = d / QB, rd = d % QB;
        scb[t] = b3;
        scy[t] = 16 + (rd / GW) * 8;
        scx[t] = 16 + (rd % GW) * 8;
        int q = min(q0 + t, Q_ - 1);
        int2 xy = g_xy2[q];
        srx[t] = xy.x; sry[t] = xy.y; srb[t] = q / QB;
    }

    int warp = t >> 5, lane = t & 31;
    int wm = warp & 3;        // 4 warps along M (32 rows each)
    int wn = warp >> 2;       // 2 warps along N (64 cols each)

    // per-thread staging addresses (two 16B segments for A and B each)
    int row0 = t >> 2,          seg0 = t & 3;
    int row1 = (t + 256) >> 2,  seg1 = (t + 256) & 3;
    const __half* srcA0 = &g_a[(size_t)min(q0 + row0, Q_ - 1) * KSP + seg0 * 8];
    const __half* srcB0 = &g_b[(size_t)min(d0 + row0, ND - 1) * KSP + seg0 * 8];
    const __half* srcA1 = &g_a[(size_t)min(q0 + row1, Q_ - 1) * KSP + seg1 * 8];
    const __half* srcB1 = &g_b[(size_t)min(d0 + row1, ND - 1) * KSP + seg1 * 8];

    float acc[2][8][4];
#pragma unroll
    for (int i = 0; i < 2; i++)
#pragma unroll
        for (int j = 0; j < 8; j++)
#pragma unroll
            for (int c = 0; c < 4; c++) acc[i][j][c] = 0.0f;

    uint4 ra0 = *(const uint4*)(srcA0);
    uint4 rb0 = *(const uint4*)(srcB0);
    uint4 ra1 = *(const uint4*)(srcA1);
    uint4 rb1 = *(const uint4*)(srcB1);

    for (int kc = 0; kc < KSP; kc += 32) {
        __syncthreads();            // previous chunk's compute finished
        *(uint4*)&As[seg0 >> 1][row0][(seg0 & 1) * 8] = ra0;
        *(uint4*)&Bs[seg0 >> 1][row0][(seg0 & 1) * 8] = rb0;
        *(uint4*)&As[seg1 >> 1][row1][(seg1 & 1) * 8] = ra1;
        *(uint4*)&Bs[seg1 >> 1][row1][(seg1 & 1) * 8] = rb1;
        __syncthreads();            // staging visible
        if (kc + 32 < KSP) {        // prefetch next chunk (overlaps MMA below)
            ra0 = *(const uint4*)(srcA0 + kc + 32);
            rb0 = *(const uint4*)(srcB0 + kc + 32);
            ra1 = *(const uint4*)(srcA1 + kc + 32);
            rb1 = *(const uint4*)(srcB1 + kc + 32);
        }
#pragma unroll
        for (int s = 0; s < 2; s++) {
            uint32_t af[2][4], bf[4][4];
            int rsel = lane & 15;
            int csel = (lane >> 4) * 8;
#pragma unroll
            for (int i = 0; i < 2; i++)
                ldsm_x4(af[i], &As[s][wm * 32 + i * 16 + rsel][csel]);
#pragma unroll
            for (int j4 = 0; j4 < 4; j4++)
                ldsm_x4(bf[j4], &Bs[s][wn * 64 + j4 * 16 + rsel][csel]);
#pragma unroll
            for (int i = 0; i < 2; i++)
#pragma unroll
                for (int j = 0; j < 8; j++)
                    mma_f16(acc[i][j], af[i], bf[j >> 1][j & 1], bf[j >> 1][(j & 1) + 2]);
        }
    }
    __syncthreads();

    // epilogue: 4 chunks of 32 rows; stage via smem, emit lane-contiguous stores
    int group = lane >> 2, tig = lane & 3;
#pragma unroll 1
    for (int w = 0; w < 4; w++) {
        if (wm == w) {
#pragma unroll
            for (int i = 0; i < 2; i++)
#pragma unroll
                for (int j = 0; j < 8; j++)
#pragma unroll
                    for (int c = 0; c < 4; c++) {
                        int rl = i * 16 + group + (c >> 1) * 8;
                        int cl = wn * 64 + j * 8 + tig * 2 + (c & 1);
                        sbuf[rl][cl] = acc[i][j][c];
                    }
        }
        __syncthreads();
        // readout: each warp owns 4 rows; lanes contiguous over columns
#pragma unroll
        for (int r4 = 0; r4 < 4; r4++) {
            int rl = warp * 4 + r4;
            int q  = q0 + w * 32 + rl;
            if (q < Q_) {
                int qx = srx[w * 32 + rl], qy = sry[w * 32 + rl], qb = srb[w * 32 + rl];
                float* so = out + (size_t)q * NCOL + 1 + NNEG;
                float* go = out + S_SCORES + (size_t)q * NCOL + 1 + NNEG;
#pragma unroll
                for (int c4 = 0; c4 < 4; c4++) {
                    int col = c4 * 32 + lane;
                    int d = d0 + col;
                    if (d0 + c4 * 32 < ND) {       // chunk-uniform validity (32 | ND-d0)
                        int dx = scx[col] - qx, dy = scy[col] - qy;
                        int dis2 = dx * dx + dy * dy + (scb[col] != qb ? 25 : 0);
                        so[d] = (dis2 < 25) ? 0.0f : sbuf[rl][col];
                        go[d] = 0.0f;
                    }
                }
            }
        }
        __syncthreads();
    }
}

// ---------------- launch ----------------
extern "C" void kernel_launch(void* const* d_in, const int* in_sizes, int n_in,
                              void* d_out, int out_size) {
    const float* feat1 = (const float*)d_in[0];
    const float* feat2 = (const float*)d_in[1];
    const float* conf1 = (const float*)d_in[2];
    const float* conf2 = (const float*)d_in[3];
    const float* aflow = (const float*)d_in[4];
    float* out = (float*)d_out;
    (void)in_sizes; (void)n_in; (void)out_size;

    k_trans_prep<<<NTB + Q_, 256>>>(feat2, feat1, conf1, aflow, out);

    k_posneg<<<Q_, 256>>>(conf2, out);

    dim3 gg(MPAD / 128, MPAD / 128);
    k_gemm<<<gg, 256>>>(out);
}